// round 2
// baseline (speedup 1.0000x reference)
#include <cuda_runtime.h>
#include <cuda_bf16.h>

// Problem constants (match reference)
#define NXg 2048
#define NYg 2048
#define INV_H  2048.0f   // 1/hx = 1/hy
#define INV_2H 1024.0f   // 1/(2hx)

#define ROWS_PER_THREAD 8
#define TPB 256          // threads per block; 2 blocks in x cover 512 quads/row

__global__ void zero_out_kernel(float* out) {
    out[0] = 0.0f;
}

__global__ __launch_bounds__(TPB)
void flow_energy_kernel(const float* __restrict__ phi, float* __restrict__ out) {
    const int quad = blockIdx.x * TPB + threadIdx.x;   // 0..511 (column quad index)
    const int j0   = quad * 4;                          // first column of this quad
    const int r0   = blockIdx.y * ROWS_PER_THREAD;      // first row of this row group
    const int qstride = NYg / 4;                        // float4 per row

    const float4* __restrict__ phi4 = reinterpret_cast<const float4*>(phi);

    // Rolling rows in registers
    float4 cur  = phi4[r0 * qstride + quad];
    float4 prev = (r0 == 0) ? cur : phi4[(r0 - 1) * qstride + quad];

    const bool left_edge  = (j0 == 0);
    const bool right_edge = (j0 + 4 == NYg);

    float acc = 0.0f;

    #pragma unroll
    for (int rr = 0; rr < ROWS_PER_THREAD; rr++) {
        const int r = r0 + rr;
        float4 next = (r == NXg - 1) ? cur : phi4[(r + 1) * qstride + quad];

        // ---- vx (row-direction gradient), sign irrelevant (squared) ----
        float vx0, vx1, vx2, vx3;
        if (r == 0) {
            vx0 = (next.x - cur.x) * INV_H;
            vx1 = (next.y - cur.y) * INV_H;
            vx2 = (next.z - cur.z) * INV_H;
            vx3 = (next.w - cur.w) * INV_H;
        } else if (r == NXg - 1) {
            vx0 = (cur.x - prev.x) * INV_H;
            vx1 = (cur.y - prev.y) * INV_H;
            vx2 = (cur.z - prev.z) * INV_H;
            vx3 = (cur.w - prev.w) * INV_H;
        } else {
            vx0 = (next.x - prev.x) * INV_2H;
            vx1 = (next.y - prev.y) * INV_2H;
            vx2 = (next.z - prev.z) * INV_2H;
            vx3 = (next.w - prev.w) * INV_2H;
        }

        // ---- vy (column-direction gradient) ----
        // Left/right scalar neighbors of this quad within row r (L1 hits:
        // adjacent threads already pulled these cache lines via float4).
        float l  = left_edge  ? 0.0f : __ldg(&phi[r * NYg + j0 - 1]);
        float rt = right_edge ? 0.0f : __ldg(&phi[r * NYg + j0 + 4]);

        float vy0 = left_edge  ? (cur.y - cur.x) * INV_H : (cur.y - l) * INV_2H;
        float vy1 = (cur.z - cur.x) * INV_2H;
        float vy2 = (cur.w - cur.y) * INV_2H;
        float vy3 = right_edge ? (cur.w - cur.z) * INV_H : (rt - cur.z) * INV_2H;

        acc += vx0 * vx0 + vx1 * vx1 + vx2 * vx2 + vx3 * vx3;
        acc += vy0 * vy0 + vy1 * vy1 + vy2 * vy2 + vy3 * vy3;

        prev = cur;
        cur  = next;
    }

    // ---- warp reduce ----
    #pragma unroll
    for (int o = 16; o > 0; o >>= 1)
        acc += __shfl_xor_sync(0xFFFFFFFFu, acc, o);

    // ---- block reduce ----
    __shared__ float warp_sums[TPB / 32];
    const int lane = threadIdx.x & 31;
    const int wid  = threadIdx.x >> 5;
    if (lane == 0) warp_sums[wid] = acc;
    __syncthreads();

    if (wid == 0) {
        float v = (lane < TPB / 32) ? warp_sums[lane] : 0.0f;
        #pragma unroll
        for (int o = 4; o > 0; o >>= 1)
            v += __shfl_xor_sync(0xFFFFFFFFu, v, o);
        if (lane == 0)
            atomicAdd(out, 0.5f * v);
    }
}

extern "C" void kernel_launch(void* const* d_in, const int* in_sizes, int n_in,
                              void* d_out, int out_size) {
    // d_in[0] = pos (unused), d_in[1] = potential_field [2048*2048] fp32
    const float* phi = (const float*)d_in[1];
    float* out = (float*)d_out;

    zero_out_kernel<<<1, 1>>>(out);

    dim3 grid(NYg / 4 / TPB, NXg / ROWS_PER_THREAD);  // (2, 256)
    flow_energy_kernel<<<grid, TPB>>>(phi, out);
}

// round 3
// speedup vs baseline: 1.0257x; 1.0257x over previous
#include <cuda_runtime.h>
#include <cuda_bf16.h>

// Problem constants (match reference)
#define NXg 2048
#define NYg 2048
#define INV_H  2048.0f   // 1/hx = 1/hy
#define INV_2H 1024.0f   // 1/(2hx)

#define ROWS_PER_THREAD 4
#define TPB 256          // threads per block; 2 blocks in x cover 512 quads/row

__global__ void zero_out_kernel(float* out) {
    out[0] = 0.0f;
}

__global__ __launch_bounds__(TPB)
void flow_energy_kernel(const float* __restrict__ phi, float* __restrict__ out) {
    const int quad = blockIdx.x * TPB + threadIdx.x;   // 0..511 (column quad index)
    const int j0   = quad * 4;                          // first column of this quad
    const int r0   = blockIdx.y * ROWS_PER_THREAD;      // first row of this row group
    const int qstride = NYg / 4;                        // float4 per row

    const float4* __restrict__ phi4 = reinterpret_cast<const float4*>(phi);

    // Rolling rows in registers
    float4 cur  = phi4[r0 * qstride + quad];
    float4 prev = (r0 == 0) ? cur : phi4[(r0 - 1) * qstride + quad];

    const bool left_edge  = (j0 == 0);
    const bool right_edge = (j0 + 4 == NYg);

    float acc = 0.0f;

    #pragma unroll
    for (int rr = 0; rr < ROWS_PER_THREAD; rr++) {
        const int r = r0 + rr;
        float4 next = (r == NXg - 1) ? cur : phi4[(r + 1) * qstride + quad];

        // ---- vx (row-direction gradient), sign irrelevant (squared) ----
        float vx0, vx1, vx2, vx3;
        if (r == 0) {
            vx0 = (next.x - cur.x) * INV_H;
            vx1 = (next.y - cur.y) * INV_H;
            vx2 = (next.z - cur.z) * INV_H;
            vx3 = (next.w - cur.w) * INV_H;
        } else if (r == NXg - 1) {
            vx0 = (cur.x - prev.x) * INV_H;
            vx1 = (cur.y - prev.y) * INV_H;
            vx2 = (cur.z - prev.z) * INV_H;
            vx3 = (cur.w - prev.w) * INV_H;
        } else {
            vx0 = (next.x - prev.x) * INV_2H;
            vx1 = (next.y - prev.y) * INV_2H;
            vx2 = (next.z - prev.z) * INV_2H;
            vx3 = (next.w - prev.w) * INV_2H;
        }

        // ---- vy (column-direction gradient) ----
        // Left/right scalar neighbors of this quad within row r (L1 hits:
        // adjacent threads already pulled these cache lines via float4).
        float l  = left_edge  ? 0.0f : __ldg(&phi[r * NYg + j0 - 1]);
        float rt = right_edge ? 0.0f : __ldg(&phi[r * NYg + j0 + 4]);

        float vy0 = left_edge  ? (cur.y - cur.x) * INV_H : (cur.y - l) * INV_2H;
        float vy1 = (cur.z - cur.x) * INV_2H;
        float vy2 = (cur.w - cur.y) * INV_2H;
        float vy3 = right_edge ? (cur.w - cur.z) * INV_H : (rt - cur.z) * INV_2H;

        acc += vx0 * vx0 + vx1 * vx1 + vx2 * vx2 + vx3 * vx3;
        acc += vy0 * vy0 + vy1 * vy1 + vy2 * vy2 + vy3 * vy3;

        prev = cur;
        cur  = next;
    }

    // ---- warp reduce ----
    #pragma unroll
    for (int o = 16; o > 0; o >>= 1)
        acc += __shfl_xor_sync(0xFFFFFFFFu, acc, o);

    // ---- block reduce ----
    __shared__ float warp_sums[TPB / 32];
    const int lane = threadIdx.x & 31;
    const int wid  = threadIdx.x >> 5;
    if (lane == 0) warp_sums[wid] = acc;
    __syncthreads();

    if (wid == 0) {
        float v = (lane < TPB / 32) ? warp_sums[lane] : 0.0f;
        #pragma unroll
        for (int o = 4; o > 0; o >>= 1)
            v += __shfl_xor_sync(0xFFFFFFFFu, v, o);
        if (lane == 0)
            atomicAdd(out, 0.5f * v);
    }
}

extern "C" void kernel_launch(void* const* d_in, const int* in_sizes, int n_in,
                              void* d_out, int out_size) {
    // d_in[0] = pos (unused), d_in[1] = potential_field [2048*2048] fp32
    const float* phi = (const float*)d_in[1];
    float* out = (float*)d_out;

    zero_out_kernel<<<1, 1>>>(out);

    dim3 grid(NYg / 4 / TPB, NXg / ROWS_PER_THREAD);  // (2, 512)
    flow_energy_kernel<<<grid, TPB>>>(phi, out);
}

// round 4
// speedup vs baseline: 1.0295x; 1.0037x over previous
#include <cuda_runtime.h>
#include <cuda_bf16.h>

// Problem constants (match reference)
#define NXg 2048
#define NYg 2048
#define INV_H  2048.0f   // 1/hx = 1/hy
#define INV_2H 1024.0f   // 1/(2hx)

#define ROWS_PER_THREAD 4
#define TPB 256          // 2 blocks in x cover 512 quads/row

__global__ void zero_out_kernel(float* out) {
    out[0] = 0.0f;
}

__global__ __launch_bounds__(TPB)
void flow_energy_kernel(const float* __restrict__ phi, float* __restrict__ out) {
    const int quad = blockIdx.x * TPB + threadIdx.x;   // column quad index (0..511)
    const int j0   = quad * 4;                          // first column of this quad
    const int r0   = blockIdx.y * ROWS_PER_THREAD;      // first row of this tile
    const int qstride = NYg / 4;

    const float4* __restrict__ phi4 = reinterpret_cast<const float4*>(phi);

    // Front-batched loads: rows r0-1 .. r0+ROWS (clamped). Clamped rows are
    // only consumed by the one-sided-difference branches where their value
    // cancels out of the formula actually used.
    float4 v[ROWS_PER_THREAD + 2];
    #pragma unroll
    for (int i = 0; i < ROWS_PER_THREAD + 2; i++) {
        int r = r0 - 1 + i;
        r = (r < 0) ? 0 : ((r > NXg - 1) ? NXg - 1 : r);
        v[i] = phi4[r * qstride + quad];
    }

    const int  lane       = threadIdx.x & 31;
    const bool left_edge  = (j0 == 0);
    const bool right_edge = (j0 + 4 == NYg);

    float acc = 0.0f;

    #pragma unroll
    for (int rr = 0; rr < ROWS_PER_THREAD; rr++) {
        const int r = r0 + rr;
        const float4 prev = v[rr];
        const float4 cur  = v[rr + 1];
        const float4 next = v[rr + 2];

        // ---- vx (row-direction gradient); sign irrelevant (squared) ----
        float vx0, vx1, vx2, vx3;
        if (r == 0) {
            vx0 = (next.x - cur.x) * INV_H;
            vx1 = (next.y - cur.y) * INV_H;
            vx2 = (next.z - cur.z) * INV_H;
            vx3 = (next.w - cur.w) * INV_H;
        } else if (r == NXg - 1) {
            vx0 = (cur.x - prev.x) * INV_H;
            vx1 = (cur.y - prev.y) * INV_H;
            vx2 = (cur.z - prev.z) * INV_H;
            vx3 = (cur.w - prev.w) * INV_H;
        } else {
            vx0 = (next.x - prev.x) * INV_2H;
            vx1 = (next.y - prev.y) * INV_2H;
            vx2 = (next.z - prev.z) * INV_2H;
            vx3 = (next.w - prev.w) * INV_2H;
        }

        // ---- vy (column-direction gradient) ----
        // Neighbors come from adjacent lanes' registers; only the warp-edge
        // lanes fall back to a (1-wavefront) predicated scalar load.
        float l  = __shfl_up_sync(0xFFFFFFFFu, cur.w, 1);
        float rt = __shfl_down_sync(0xFFFFFFFFu, cur.x, 1);
        if (lane == 0 && !left_edge)
            l = __ldg(&phi[r * NYg + j0 - 1]);
        if (lane == 31 && !right_edge)
            rt = __ldg(&phi[r * NYg + j0 + 4]);

        float vy0 = left_edge  ? (cur.y - cur.x) * INV_H : (cur.y - l) * INV_2H;
        float vy1 = (cur.z - cur.x) * INV_2H;
        float vy2 = (cur.w - cur.y) * INV_2H;
        float vy3 = right_edge ? (cur.w - cur.z) * INV_H : (rt - cur.z) * INV_2H;

        acc += vx0 * vx0 + vx1 * vx1 + vx2 * vx2 + vx3 * vx3;
        acc += vy0 * vy0 + vy1 * vy1 + vy2 * vy2 + vy3 * vy3;
    }

    // ---- warp reduce ----
    #pragma unroll
    for (int o = 16; o > 0; o >>= 1)
        acc += __shfl_xor_sync(0xFFFFFFFFu, acc, o);

    // ---- block reduce ----
    __shared__ float warp_sums[TPB / 32];
    const int wid = threadIdx.x >> 5;
    if (lane == 0) warp_sums[wid] = acc;
    __syncthreads();

    if (wid == 0) {
        float s = (lane < TPB / 32) ? warp_sums[lane] : 0.0f;
        #pragma unroll
        for (int o = 4; o > 0; o >>= 1)
            s += __shfl_xor_sync(0xFFFFFFFFu, s, o);
        if (lane == 0)
            atomicAdd(out, 0.5f * s);
    }
}

extern "C" void kernel_launch(void* const* d_in, const int* in_sizes, int n_in,
                              void* d_out, int out_size) {
    // d_in[0] = pos (unused), d_in[1] = potential_field [2048*2048] fp32
    const float* phi = (const float*)d_in[1];
    float* out = (float*)d_out;

    zero_out_kernel<<<1, 1>>>(out);

    dim3 grid(NYg / 4 / TPB, NXg / ROWS_PER_THREAD);  // (2, 512)
    flow_energy_kernel<<<grid, TPB>>>(phi, out);
}